// round 1
// baseline (speedup 1.0000x reference)
#include <cuda_runtime.h>
#include <math.h>

#define HH 1024
#define WW 1024
#define NPIX (HH * WW)

// Static device scratch (no allocations allowed).
// g_edges[0] = pred edges, g_edges[1] = target edges
// g_g2[0]    = pred row-pass squared distances, g_g2[1] = target
__device__ float g_edges[2][NPIX];
__device__ float g_g2[2][NPIX];
__device__ float g_sums[2];

// ---------------------------------------------------------------------------
// Kernel 1: edge maps for both images. edge = seg - eroded, where
// eroded(y,x) = 1 iff 3x3 box conv (zero-padded) == 9, i.e. interior pixel
// with all nine values == 1. Also zeroes the accumulators (each graph replay).
// ---------------------------------------------------------------------------
__global__ void edges_kernel(const float* __restrict__ preds,
                             const float* __restrict__ targets) {
    int img = blockIdx.y;
    int idx = blockIdx.x * blockDim.x + threadIdx.x;
    if (img == 0 && blockIdx.x == 0 && threadIdx.x < 2)
        g_sums[threadIdx.x] = 0.0f;
    if (idx >= NPIX) return;
    const float* __restrict__ seg = (img == 0) ? preds : targets;
    int y = idx / WW, x = idx % WW;
    float s = seg[idx];
    float eroded = 0.0f;
    if (s == 1.0f && y > 0 && y < HH - 1 && x > 0 && x < WW - 1) {
        bool all1 = true;
        #pragma unroll
        for (int dy = -1; dy <= 1; dy++) {
            #pragma unroll
            for (int dx = -1; dx <= 1; dx++) {
                all1 = all1 && (seg[(y + dy) * WW + (x + dx)] == 1.0f);
            }
        }
        eroded = all1 ? 1.0f : 0.0f;
    }
    g_edges[img][idx] = s - eroded;
}

// ---------------------------------------------------------------------------
// Kernel 2: per-row 1D distance to nearest edge pixel, squared.
// One block (1024 threads) per (row, image). Feature flags in shared memory;
// each thread scans outward — expected depth ~2 with dense random edges.
// Exactly replicates: g = nearest integer distance, or 1e6 if the row has
// no edge pixel; g2 = g*g (all exact in f32 within these ranges).
// ---------------------------------------------------------------------------
__global__ void row_edt_kernel() {
    __shared__ unsigned char feat[WW];
    int img = blockIdx.y;
    int row = blockIdx.x;
    int j = threadIdx.x;
    const float* __restrict__ e = g_edges[img] + row * WW;
    feat[j] = (e[j] == 1.0f) ? 1 : 0;
    __syncthreads();
    float g;
    if (feat[j]) {
        g = 0.0f;
    } else {
        int r = 1;
        for (; r < WW; r++) {
            int jl = j - r, jr = j + r;
            bool hit = (jl >= 0 && feat[jl]) || (jr < WW && feat[jr]);
            if (hit) break;
        }
        g = (r < WW) ? (float)r : 1e6f;
    }
    g_g2[img][row * WW + j] = g * g;
}

// ---------------------------------------------------------------------------
// Kernel 3: column lower-envelope min with early exit + fused weighted sum.
// blockIdx.y = img: img 0 -> pred_dt (g2[0]) weighted by target edges (edges[1])
//              img 1 -> target_dt (g2[1]) weighted by pred edges (edges[0])
// D2[i][j] = min_k g2[k][j] + (i-k)^2; once r^2 >= best no farther k can win.
// Candidate values are computed identically to the reference (f32 add of
// g2 and exact-integer r^2), so the min is bit-identical.
// ---------------------------------------------------------------------------
__global__ void col_edt_reduce_kernel() {
    int img = blockIdx.y;
    int idx = blockIdx.x * blockDim.x + threadIdx.x;
    float val = 0.0f;
    if (idx < NPIX) {
        float wgt = g_edges[1 - img][idx];
        if (wgt != 0.0f) {
            int i = idx / WW, j = idx % WW;
            const float* __restrict__ g2 = g_g2[img];
            float best = g2[idx];
            for (int r = 1; r < HH; r++) {
                float rr = (float)(r * r);
                if (rr >= best) break;
                int ku = i - r, kd = i + r;
                if (ku >= 0) {
                    float d = g2[ku * WW + j] + rr;
                    if (d < best) best = d;
                }
                if (kd < HH) {
                    float d = g2[kd * WW + j] + rr;
                    if (d < best) best = d;
                }
            }
            val = wgt * sqrtf(best);
        }
    }
    // block reduction: warp shuffle, then shared across warps
    __shared__ float warpsum[8];  // blockDim 256 -> 8 warps
    #pragma unroll
    for (int off = 16; off > 0; off >>= 1)
        val += __shfl_down_sync(0xffffffffu, val, off);
    int lane = threadIdx.x & 31;
    int wid = threadIdx.x >> 5;
    if (lane == 0) warpsum[wid] = val;
    __syncthreads();
    if (wid == 0) {
        val = (lane < (blockDim.x >> 5)) ? warpsum[lane] : 0.0f;
        #pragma unroll
        for (int off = 4; off > 0; off >>= 1)
            val += __shfl_down_sync(0xffffffffu, val, off);
        if (lane == 0) atomicAdd(&g_sums[img], val);
    }
}

// ---------------------------------------------------------------------------
// Kernel 4: finalize scalar: sigmoid((mean1 + mean2) / 2)
// ---------------------------------------------------------------------------
__global__ void finalize_kernel(float* __restrict__ out) {
    float invN = 1.0f / (float)NPIX;
    float loss = (g_sums[0] * invN + g_sums[1] * invN) * 0.5f;
    out[0] = 1.0f / (1.0f + expf(-loss));
}

extern "C" void kernel_launch(void* const* d_in, const int* in_sizes, int n_in,
                              void* d_out, int out_size) {
    const float* preds = (const float*)d_in[0];
    const float* targets = (const float*)d_in[1];
    float* out = (float*)d_out;

    dim3 blk(256);
    dim3 grdPix((NPIX + 255) / 256, 2);

    edges_kernel<<<grdPix, blk>>>(preds, targets);
    row_edt_kernel<<<dim3(HH, 2), dim3(WW)>>>();
    col_edt_reduce_kernel<<<grdPix, blk>>>();
    finalize_kernel<<<1, 1>>>(out);
}

// round 2
// speedup vs baseline: 1.2183x; 1.2183x over previous
#include <cuda_runtime.h>
#include <math.h>

#define HH 1024
#define WW 1024
#define NPIX (HH * WW)
#define BLK_B 256
#define TOTAL_B ((NPIX / BLK_B) * 2)

// Static device scratch (no allocations allowed).
__device__ unsigned char  g_edge[2][NPIX];   // edge flags (0/1)
__device__ unsigned short g_g[2][NPIX];      // per-row 1D distance (0xFFFF = no feature in row)
__device__ float          g_sums[2];
__device__ unsigned int   g_count;

// ---------------------------------------------------------------------------
// Kernel A: fused edges + row EDT. One block per (row, img), 1024 threads.
// Edge(y,x) = (seg==1) && !(3x3 all-ones interior). Then per-row outward scan
// to nearest edge (expected depth ~2 at edge density 0.5). Stores edge flags
// (uchar) and row distance g (u16; 0xFFFF sentinel = featureless row).
// Also zeroes the accumulators + ticket counter for each graph replay.
// ---------------------------------------------------------------------------
__global__ void edges_row_kernel(const float* __restrict__ preds,
                                 const float* __restrict__ targets) {
    __shared__ unsigned char a0[WW], a1[WW], a2[WW], ft[WW];
    int img = blockIdx.y;
    int y   = blockIdx.x;
    int j   = threadIdx.x;
    if (img == 0 && y == 0 && j < 3) {
        if (j < 2) g_sums[j] = 0.0f; else g_count = 0u;
    }
    const float* __restrict__ seg = (img == 0) ? preds : targets;
    float c = seg[y * WW + j];
    a1[j] = (c == 1.0f);
    a0[j] = (y > 0)      ? (seg[(y - 1) * WW + j] == 1.0f) : 0;
    a2[j] = (y < HH - 1) ? (seg[(y + 1) * WW + j] == 1.0f) : 0;
    __syncthreads();
    unsigned char eroded = 0;
    if (a1[j] && j > 0 && j < WW - 1 && y > 0 && y < HH - 1) {
        eroded = a0[j-1] & a0[j] & a0[j+1]
               & a1[j-1]         & a1[j+1]
               & a2[j-1] & a2[j] & a2[j+1];
    }
    unsigned char f = a1[j] && !eroded;
    ft[j] = f;
    g_edge[img][y * WW + j] = f;
    __syncthreads();
    unsigned short gv;
    if (f) {
        gv = 0;
    } else {
        int r = 1;
        for (; r < WW; r++) {
            int jl = j - r, jr = j + r;
            if ((jl >= 0 && ft[jl]) || (jr < WW && ft[jr])) break;
        }
        gv = (r < WW) ? (unsigned short)r : (unsigned short)0xFFFF;
    }
    g_g[img][y * WW + j] = gv;
}

// ---------------------------------------------------------------------------
// Kernel B: column lower-envelope min (early exit r^2 >= best), weighted by
// the OTHER image's edge flag, block reduction, atomic accumulate, and
// last-block finalize (fence + ticket) -> sigmoid scalar in d_out.
// Candidates computed identically to the reference (f32 g*g + exact r^2),
// so the min is bit-identical. Sentinel reconstructs g = 1e6 - col.
// ---------------------------------------------------------------------------
__global__ void col_reduce_finalize_kernel(float* __restrict__ out) {
    int img = blockIdx.y;
    int idx = blockIdx.x * blockDim.x + threadIdx.x;
    int j = idx & (WW - 1);
    int i = idx >> 10;
    float val = 0.0f;
    if (g_edge[1 - img][idx]) {
        const unsigned short* __restrict__ gg = g_g[img];
        float sent = 1e6f - (float)j;
        unsigned short gu = gg[idx];
        float gf = (gu == 0xFFFFu) ? sent : (float)gu;
        float best = gf * gf;
        for (int r = 1; r < HH; r++) {
            float rr = (float)(r * r);
            if (rr >= best) break;
            int ku = i - r, kd = i + r;
            if (ku >= 0) {
                unsigned short u = gg[ku * WW + j];
                float f2 = (u == 0xFFFFu) ? sent : (float)u;
                float d = f2 * f2 + rr;
                if (d < best) best = d;
            }
            if (kd < HH) {
                unsigned short u = gg[kd * WW + j];
                float f2 = (u == 0xFFFFu) ? sent : (float)u;
                float d = f2 * f2 + rr;
                if (d < best) best = d;
            }
        }
        val = sqrtf(best);
    }
    // block reduction
    __shared__ float warpsum[BLK_B / 32];
    #pragma unroll
    for (int off = 16; off > 0; off >>= 1)
        val += __shfl_down_sync(0xffffffffu, val, off);
    int lane = threadIdx.x & 31;
    int wid  = threadIdx.x >> 5;
    if (lane == 0) warpsum[wid] = val;
    __syncthreads();
    if (wid == 0) {
        val = (lane < (BLK_B >> 5)) ? warpsum[lane] : 0.0f;
        #pragma unroll
        for (int off = 4; off > 0; off >>= 1)
            val += __shfl_down_sync(0xffffffffu, val, off);
        if (lane == 0) {
            atomicAdd(&g_sums[img], val);
            __threadfence();
            unsigned int t = atomicAdd(&g_count, 1u);
            if (t == (unsigned int)(TOTAL_B - 1)) {
                // all blocks' sums are visible (each fenced before its ticket)
                float s0 = atomicAdd(&g_sums[0], 0.0f);
                float s1 = atomicAdd(&g_sums[1], 0.0f);
                float invN = 1.0f / (float)NPIX;
                float loss = (s0 * invN + s1 * invN) * 0.5f;
                out[0] = 1.0f / (1.0f + expf(-loss));
            }
        }
    }
}

extern "C" void kernel_launch(void* const* d_in, const int* in_sizes, int n_in,
                              void* d_out, int out_size) {
    const float* preds   = (const float*)d_in[0];
    const float* targets = (const float*)d_in[1];
    float* out = (float*)d_out;

    edges_row_kernel<<<dim3(HH, 2), dim3(WW)>>>(preds, targets);
    col_reduce_finalize_kernel<<<dim3(NPIX / BLK_B, 2), dim3(BLK_B)>>>(out);
}

// round 3
// speedup vs baseline: 1.2846x; 1.0544x over previous
#include <cuda_runtime.h>
#include <math.h>

#define HH 1024
#define WW 1024
#define NPIX (HH * WW)
#define R_STRIP 16
#define BLK_B 256
#define PPT 4                              // pixels per thread in kernel B
#define TOTAL_B ((NPIX / PPT / BLK_B) * 2) // ticket count for finalize

__device__ unsigned char  g_edge[2][NPIX];  // edge flags (0/1)
__device__ unsigned short g_g[2][NPIX];     // row 1D distance (0xFFFF = featureless row)
__device__ float          g_sums[2];
__device__ unsigned int   g_count;

// ---------------------------------------------------------------------------
// Kernel A: strip-fused edges + row EDT. One 1024-thread block per
// (16-row strip, image). Flags for strip+halo live in shared (loaded once),
// then per row: edge = seg && !(3x3 all-ones), row scan to nearest edge.
// Also zeroes accumulators/ticket each replay.
// ---------------------------------------------------------------------------
__global__ void __launch_bounds__(WW) edges_row_kernel(
        const float* __restrict__ preds, const float* __restrict__ targets) {
    __shared__ unsigned char sflag[R_STRIP + 2][WW];
    __shared__ unsigned char sfeat[WW];
    int img = blockIdx.y;
    int strip = blockIdx.x;
    int j = threadIdx.x;
    int y0 = strip * R_STRIP;
    if (img == 0 && strip == 0 && j < 3) {
        if (j < 2) g_sums[j] = 0.0f; else g_count = 0u;
    }
    const float* __restrict__ seg = (img == 0) ? preds : targets;
    #pragma unroll
    for (int rr = 0; rr < R_STRIP + 2; rr++) {
        int y = y0 + rr - 1;
        sflag[rr][j] = (y >= 0 && y < HH) ? (seg[y * WW + j] == 1.0f) : 0;
    }
    __syncthreads();
    for (int rloc = 0; rloc < R_STRIP; rloc++) {
        int y = y0 + rloc;
        int rs = rloc + 1;
        unsigned char s = sflag[rs][j];
        unsigned char er = 0;
        if (s && j > 0 && j < WW - 1 && y > 0 && y < HH - 1) {
            er = sflag[rs-1][j-1] & sflag[rs-1][j] & sflag[rs-1][j+1]
               & sflag[rs  ][j-1]                  & sflag[rs  ][j+1]
               & sflag[rs+1][j-1] & sflag[rs+1][j] & sflag[rs+1][j+1];
        }
        unsigned char f = (unsigned char)(s && !er);
        sfeat[j] = f;
        g_edge[img][y * WW + j] = f;
        __syncthreads();
        unsigned short gv;
        if (f) {
            gv = 0;
        } else {
            int r = 1;
            for (; r < WW; r++) {
                int jl = j - r, jr = j + r;
                if ((jl >= 0 && sfeat[jl]) || (jr < WW && sfeat[jr])) break;
            }
            gv = (r < WW) ? (unsigned short)r : (unsigned short)0xFFFF;
        }
        g_g[img][y * WW + j] = gv;
        __syncthreads();
    }
}

// ---------------------------------------------------------------------------
// Kernel B: column lower-envelope min, 4 horizontal pixels per thread.
// Group early-exit on max(best): extra iterations only test candidates
// >= r^2 >= best, so the min (and the result) is exactly the reference's.
// Unweighted lanes keep best = 0 and never drive the loop.
// Fused block reduction + ticket finalize -> sigmoid scalar.
// ---------------------------------------------------------------------------
__global__ void __launch_bounds__(BLK_B) col_reduce_finalize_kernel(float* __restrict__ out) {
    int img = blockIdx.y;
    int t = blockIdx.x * blockDim.x + threadIdx.x;   // 0 .. NPIX/4-1
    int idx4 = t * PPT;
    int j0 = idx4 & (WW - 1);
    int i  = idx4 >> 10;
    float val = 0.0f;
    uchar4 w4 = *(const uchar4*)&g_edge[1 - img][idx4];
    if (w4.x | w4.y | w4.z | w4.w) {
        const unsigned short* __restrict__ gg = g_g[img];
        unsigned char wa[4] = {w4.x, w4.y, w4.z, w4.w};
        ushort4 gv4 = *(const ushort4*)&gg[idx4];
        unsigned short ga[4] = {gv4.x, gv4.y, gv4.z, gv4.w};
        float best[4];
        float need = 0.0f;
        #pragma unroll
        for (int c = 0; c < 4; c++) {
            float gf = (ga[c] == 0xFFFFu) ? (1e6f - (float)(j0 + c)) : (float)ga[c];
            best[c] = wa[c] ? gf * gf : 0.0f;
            need = fmaxf(need, best[c]);
        }
        for (int r = 1; r < HH; r++) {
            float rr = (float)(r * r);
            if (rr >= need) break;
            int ku = i - r, kd = i + r;
            if (ku >= 0) {
                ushort4 u4 = *(const ushort4*)&gg[ku * WW + j0];
                unsigned short ua[4] = {u4.x, u4.y, u4.z, u4.w};
                #pragma unroll
                for (int c = 0; c < 4; c++) {
                    float f2 = (ua[c] == 0xFFFFu) ? (1e6f - (float)(j0 + c)) : (float)ua[c];
                    float d = f2 * f2 + rr;
                    best[c] = fminf(best[c], d);
                }
            }
            if (kd < HH) {
                ushort4 u4 = *(const ushort4*)&gg[kd * WW + j0];
                unsigned short ua[4] = {u4.x, u4.y, u4.z, u4.w};
                #pragma unroll
                for (int c = 0; c < 4; c++) {
                    float f2 = (ua[c] == 0xFFFFu) ? (1e6f - (float)(j0 + c)) : (float)ua[c];
                    float d = f2 * f2 + rr;
                    best[c] = fminf(best[c], d);
                }
            }
            need = fmaxf(fmaxf(best[0], best[1]), fmaxf(best[2], best[3]));
        }
        #pragma unroll
        for (int c = 0; c < 4; c++)
            if (wa[c]) val += sqrtf(best[c]);
    }
    // block reduction
    __shared__ float warpsum[BLK_B / 32];
    #pragma unroll
    for (int off = 16; off > 0; off >>= 1)
        val += __shfl_down_sync(0xffffffffu, val, off);
    int lane = threadIdx.x & 31;
    int wid  = threadIdx.x >> 5;
    if (lane == 0) warpsum[wid] = val;
    __syncthreads();
    if (wid == 0) {
        val = (lane < (BLK_B >> 5)) ? warpsum[lane] : 0.0f;
        #pragma unroll
        for (int off = 4; off > 0; off >>= 1)
            val += __shfl_down_sync(0xffffffffu, val, off);
        if (lane == 0) {
            atomicAdd(&g_sums[img], val);
            __threadfence();
            unsigned int tkt = atomicAdd(&g_count, 1u);
            if (tkt == (unsigned int)(TOTAL_B - 1)) {
                float s0 = atomicAdd(&g_sums[0], 0.0f);
                float s1 = atomicAdd(&g_sums[1], 0.0f);
                float invN = 1.0f / (float)NPIX;
                float loss = (s0 * invN + s1 * invN) * 0.5f;
                out[0] = 1.0f / (1.0f + expf(-loss));
            }
        }
    }
}

extern "C" void kernel_launch(void* const* d_in, const int* in_sizes, int n_in,
                              void* d_out, int out_size) {
    const float* preds   = (const float*)d_in[0];
    const float* targets = (const float*)d_in[1];
    float* out = (float*)d_out;

    edges_row_kernel<<<dim3(HH / R_STRIP, 2), dim3(WW)>>>(preds, targets);
    col_reduce_finalize_kernel<<<dim3(NPIX / PPT / BLK_B, 2), dim3(BLK_B)>>>(out);
}